// round 10
// baseline (speedup 1.0000x reference)
#include <cuda_runtime.h>
#include <cstdint>

#define N_MAX   100000
#define E_MAX   1600000
#define NG      64
#define NHID    64
#define NCLASS  10

// ---------------- scratch (static device memory; no runtime allocation) ----
__device__ __align__(16) int   g_cnt[N_MAX + 1];
__device__ __align__(16) int   g_rowptr[N_MAX + 1];
__device__ __align__(16) int   g_wpos[N_MAX];
__device__ __align__(16) float g_dinv[N_MAX];
__device__ __align__(16) int   g_col[E_MAX];
__device__ __align__(16) float g_enorm[E_MAX];
__device__ __align__(16) float g_bufA[(size_t)N_MAX * NHID];   // matmul out / spmm in
__device__ __align__(16) float g_bufB[(size_t)N_MAX * NHID];   // spmm out / next matmul in
__device__ __align__(16) float g_pooled[NG * NHID];
__device__ __align__(16) float g_gcnt[NG];
__device__ int g_idx64;   // 1 if edge_index/batch are int64, 0 if int32

// ---- dtype detection: int64 little-endian => odd 32-bit words all zero ----
__global__ void detect_kernel(const int* __restrict__ ei)
{
    int nz = 0;
    for (int i = 0; i < 64; ++i) nz += (ei[2 * i + 1] != 0);
    g_idx64 = (nz == 0) ? 1 : 0;
}

// index fetch helpers (branch on detected dtype)
__device__ __forceinline__ int edge_at(const int* __restrict__ ei, int row, int e,
                                       int E, int idx64)
{
    size_t elem = (size_t)row * E + e;
    return idx64 ? ei[elem * 2] : ei[elem];
}
__device__ __forceinline__ int batch_at(const int* __restrict__ b, int r, int idx64)
{
    return idx64 ? b[(size_t)r * 2] : b[r];
}

// ---------------- init: zero histogram + pool accumulators ----------------
__global__ void init_kernel(int n)
{
    int i = blockIdx.x * blockDim.x + threadIdx.x;
    if (i <= n)        g_cnt[i] = 0;
    if (i < NG * NHID) g_pooled[i] = 0.f;
    if (i < NG)        g_gcnt[i] = 0.f;
}

// ---------------- degree histogram over dst -------------------------------
__global__ void hist_kernel(const int* __restrict__ ei, int E)
{
    int e = blockIdx.x * blockDim.x + threadIdx.x;
    if (e >= E) return;
    int idx64 = g_idx64;
    int d = edge_at(ei, 1, e, E, idx64);
    atomicAdd(&g_cnt[d], 1);
}

// ---------------- dinv = rsqrt(indeg + 1 self loop) -----------------------
__global__ void dinv_kernel(int n)
{
    int i = blockIdx.x * blockDim.x + threadIdx.x;
    if (i < n) g_dinv[i] = rsqrtf((float)(g_cnt[i] + 1));
}

// ---------------- single-block exclusive scan -> rowptr, wpos -------------
__global__ void scan_kernel(int n)
{
    __shared__ int ssum[1024];
    int tid = threadIdx.x;
    int per = (n + 1023) / 1024;
    int beg = tid * per;
    int end = min(beg + per, n);
    int s = 0;
    for (int i = beg; i < end; ++i) s += g_cnt[i];
    ssum[tid] = s;
    __syncthreads();
    // Hillis-Steele inclusive scan
    for (int off = 1; off < 1024; off <<= 1) {
        int add = (tid >= off) ? ssum[tid - off] : 0;
        __syncthreads();
        ssum[tid] += add;
        __syncthreads();
    }
    int run = (tid == 0) ? 0 : ssum[tid - 1];
    for (int i = beg; i < end; ++i) {
        g_rowptr[i] = run;
        g_wpos[i]   = run;
        run += g_cnt[i];
    }
    if (end == n) g_rowptr[n] = run;   // total E (all tail threads write same value)
}

// ---------------- bucket edges by dst (CSR build) -------------------------
__global__ void scatter_kernel(const int* __restrict__ ei, int E)
{
    int e = blockIdx.x * blockDim.x + threadIdx.x;
    if (e >= E) return;
    int idx64 = g_idx64;
    int s = edge_at(ei, 0, e, E, idx64);
    int d = edge_at(ei, 1, e, E, idx64);
    int pos = atomicAdd(&g_wpos[d], 1);
    g_col[pos]   = s;
    g_enorm[pos] = g_dinv[s] * g_dinv[d];
}

// ------- dense matmul body: out[M,64] = X[M,K] @ W[K,64] (256 thr) --------
template<int K>
__device__ __forceinline__ void matmul_body(const float* __restrict__ X,
                                            const float* __restrict__ W,
                                            float* __restrict__ out, int M)
{
    constexpr int KC = 64, BM = 64;
    __shared__ float Ws[KC][NHID];
    __shared__ float Xs[BM][KC + 1];
    int r0 = blockIdx.x * BM;
    int tx = threadIdx.x & 15;   // col group 0..15
    int ty = threadIdx.x >> 4;   // row group 0..15
    float acc[4][4] = {};
    for (int kc = 0; kc < K; kc += KC) {
        for (int i = threadIdx.x; i < KC * NHID; i += 256) {
            int k = i / NHID, c = i % NHID;
            Ws[k][c] = W[(size_t)(kc + k) * NHID + c];
        }
        for (int i = threadIdx.x; i < BM * KC; i += 256) {
            int r = i / KC, k = i % KC;
            Xs[r][k] = (r0 + r < M) ? X[(size_t)(r0 + r) * K + kc + k] : 0.f;
        }
        __syncthreads();
#pragma unroll
        for (int k = 0; k < KC; ++k) {
            float x0 = Xs[ty * 4 + 0][k];
            float x1 = Xs[ty * 4 + 1][k];
            float x2 = Xs[ty * 4 + 2][k];
            float x3 = Xs[ty * 4 + 3][k];
            float4 wv = *(const float4*)&Ws[k][tx * 4];
            acc[0][0] += x0 * wv.x; acc[0][1] += x0 * wv.y; acc[0][2] += x0 * wv.z; acc[0][3] += x0 * wv.w;
            acc[1][0] += x1 * wv.x; acc[1][1] += x1 * wv.y; acc[1][2] += x1 * wv.z; acc[1][3] += x1 * wv.w;
            acc[2][0] += x2 * wv.x; acc[2][1] += x2 * wv.y; acc[2][2] += x2 * wv.z; acc[2][3] += x2 * wv.w;
            acc[3][0] += x3 * wv.x; acc[3][1] += x3 * wv.y; acc[3][2] += x3 * wv.z; acc[3][3] += x3 * wv.w;
        }
        __syncthreads();
    }
#pragma unroll
    for (int i = 0; i < 4; ++i) {
        int r = r0 + ty * 4 + i;
        if (r < M) {
            float4 v = make_float4(acc[i][0], acc[i][1], acc[i][2], acc[i][3]);
            *(float4*)&out[(size_t)r * NHID + tx * 4] = v;
        }
    }
}

// layer 1: external x -> g_bufA
__global__ void matmul_l1(const float* __restrict__ X,
                          const float* __restrict__ W, int M)
{
    matmul_body<128>(X, W, g_bufA, M);
}
// layers 2,3: g_bufB -> g_bufA
__global__ void matmul_l23(const float* __restrict__ W, int M)
{
    matmul_body<64>(g_bufB, W, g_bufA, M);
}

// ------- SpMM aggregation (g_bufA -> g_bufB), warp per node ---------------
// fuses self-loop + bias + ReLU
__global__ void spmm_kernel(const float* __restrict__ bias, int n)
{
    int node = (blockIdx.x * blockDim.x + threadIdx.x) >> 5;
    if (node >= n) return;
    int lane = threadIdx.x & 31;
    const float* __restrict__ h = g_bufA;

    int beg = g_rowptr[node], end = g_rowptr[node + 1];
    float di = g_dinv[node];
    float2 hv = *(const float2*)(h + (size_t)node * NHID + lane * 2);
    float sl = di * di;
    float ax = hv.x * sl;
    float ay = hv.y * sl;

    int e = beg;
    for (; e + 4 <= end; e += 4) {
        int   s0 = g_col[e],     s1 = g_col[e + 1],   s2 = g_col[e + 2],   s3 = g_col[e + 3];
        float w0 = g_enorm[e],   w1 = g_enorm[e + 1], w2 = g_enorm[e + 2], w3 = g_enorm[e + 3];
        float2 v0 = *(const float2*)(h + (size_t)s0 * NHID + lane * 2);
        float2 v1 = *(const float2*)(h + (size_t)s1 * NHID + lane * 2);
        float2 v2 = *(const float2*)(h + (size_t)s2 * NHID + lane * 2);
        float2 v3 = *(const float2*)(h + (size_t)s3 * NHID + lane * 2);
        ax += v0.x * w0; ay += v0.y * w0;
        ax += v1.x * w1; ay += v1.y * w1;
        ax += v2.x * w2; ay += v2.y * w2;
        ax += v3.x * w3; ay += v3.y * w3;
    }
    for (; e < end; ++e) {
        int s = g_col[e]; float w = g_enorm[e];
        float2 v = *(const float2*)(h + (size_t)s * NHID + lane * 2);
        ax += v.x * w; ay += v.y * w;
    }

    float bx = bias[lane * 2], by = bias[lane * 2 + 1];
    float2 res = make_float2(fmaxf(ax + bx, 0.f), fmaxf(ay + by, 0.f));
    *(float2*)(g_bufB + (size_t)node * NHID + lane * 2) = res;
}

// ---------------- mean pool partials (batch is sorted; reads g_bufB) ------
__global__ void pool_kernel(const int* __restrict__ batch, int n)
{
    const int ROWS = 256;
    int f  = threadIdx.x;                 // 64 threads, one feature each
    int r0 = blockIdx.x * ROWS;
    if (r0 >= n) return;
    int idx64 = g_idx64;
    int r1 = min(r0 + ROWS, n);
    int cur = batch_at(batch, r0, idx64);
    int start = r0;
    float acc = 0.f;
    for (int r = r0; r < r1; ++r) {
        int gg = batch_at(batch, r, idx64);
        if (gg != cur) {
            atomicAdd(&g_pooled[cur * NHID + f], acc);
            if (f == 0) atomicAdd(&g_gcnt[cur], (float)(r - start));
            acc = 0.f; cur = gg; start = r;
        }
        acc += g_bufB[(size_t)r * NHID + f];
    }
    atomicAdd(&g_pooled[cur * NHID + f], acc);
    if (f == 0) atomicAdd(&g_gcnt[cur], (float)(r1 - start));
}

// ---------------- head: mean, linear, softmax -----------------------------
__global__ void head_kernel(const float* __restrict__ Wl,
                            const float* __restrict__ bl,
                            float* __restrict__ out)
{
    int g = threadIdx.x;                  // 64 graphs
    float c   = fmaxf(g_gcnt[g], 1.f);
    float inv = 1.f / c;
    float logits[NCLASS];
#pragma unroll
    for (int j = 0; j < NCLASS; ++j) logits[j] = bl[j];
    for (int k = 0; k < NHID; ++k) {
        float p = g_pooled[g * NHID + k] * inv;
#pragma unroll
        for (int j = 0; j < NCLASS; ++j) logits[j] += p * Wl[k * NCLASS + j];
    }
    float m = logits[0];
#pragma unroll
    for (int j = 1; j < NCLASS; ++j) m = fmaxf(m, logits[j]);
    float s = 0.f;
#pragma unroll
    for (int j = 0; j < NCLASS; ++j) { logits[j] = expf(logits[j] - m); s += logits[j]; }
    float si = 1.f / s;
#pragma unroll
    for (int j = 0; j < NCLASS; ++j) out[g * NCLASS + j] = logits[j] * si;
}

// ---------------- launch (pure kernel launches; graph-capturable) ---------
extern "C" void kernel_launch(void* const* d_in, const int* in_sizes, int n_in,
                              void* d_out, int out_size)
{
    const float* x     = (const float*)d_in[0];
    const int*   ei    = (const int*)d_in[1];     // int32 or int64 (auto-detected)
    const int*   batch = (const int*)d_in[2];
    const float* W1 = (const float*)d_in[3];
    const float* b1 = (const float*)d_in[4];
    const float* W2 = (const float*)d_in[5];
    const float* b2 = (const float*)d_in[6];
    const float* W3 = (const float*)d_in[7];
    const float* b3 = (const float*)d_in[8];
    const float* Wl = (const float*)d_in[9];
    const float* bl = (const float*)d_in[10];
    float* out = (float*)d_out;

    int n = in_sizes[0] / 128;       // 100000
    int E = in_sizes[1] / 2;         // 1600000 (element count, dtype-independent)

    // graph preprocessing (reused by all 3 layers)
    detect_kernel<<<1, 1>>>(ei);
    init_kernel<<<(n + 256) / 256, 256>>>(n);
    hist_kernel<<<(E + 255) / 256, 256>>>(ei, E);
    dinv_kernel<<<(n + 255) / 256, 256>>>(n);
    scan_kernel<<<1, 1024>>>(n);
    scatter_kernel<<<(E + 255) / 256, 256>>>(ei, E);

    int mm_grid   = (n + 63) / 64;
    int spmm_grid = (n * 32 + 255) / 256;

    // layer 1 (K=128): x -> A, A -> B
    matmul_l1<<<mm_grid, 256>>>(x, W1, n);
    spmm_kernel<<<spmm_grid, 256>>>(b1, n);
    // layer 2 (K=64): B -> A, A -> B
    matmul_l23<<<mm_grid, 256>>>(W2, n);
    spmm_kernel<<<spmm_grid, 256>>>(b2, n);
    // layer 3 (K=64): B -> A, A -> B
    matmul_l23<<<mm_grid, 256>>>(W3, n);
    spmm_kernel<<<spmm_grid, 256>>>(b3, n);

    // mean pool + head
    pool_kernel<<<(n + 255) / 256, 64>>>(batch, n);
    head_kernel<<<1, 64>>>(Wl, bl, out);
}